// round 12
// baseline (speedup 1.0000x reference)
#include <cuda_runtime.h>
#include <cuda_fp16.h>
#include <cstdint>
#include <cfloat>

// Problem constants
#define NF    1024
#define BATCH 1024
#define HW    64
#define PIX   (HW * HW)     // 4096
#define PAD   3
#define PW    70            // padded side
#define PPIX  (PW * PW)     // 4900
#define ROWB  5120          // bytes per staged row: 10 px * 256 batch * 2B
#define NSTG  4             // cp.async ring stages

// 10 MB scratch: zero-PADDED image, fp16, transposed to [padded_pixel][batch].
// __device__ globals are zero-initialized at module load (fp16 zero == 0x0000)
// and the transpose never writes the 3-wide border -> no bounds checks needed.
__device__ __half g_xh[(size_t)PPIX * BATCH];

// ---------------------------------------------------------------------------
// Kernel 1: transpose + fp32->fp16 convert.  X [B, 4096] -> g_xh interior.
// ---------------------------------------------------------------------------
__global__ void xt_transpose_kernel(const float* __restrict__ X) {
    __shared__ float tile[32][65];          // [pixel_local][batch_local]
    const int p0 = blockIdx.x * 32;
    const int b0 = blockIdx.y * 64;
    const int tx = threadIdx.x;             // block (32, 8)
    const int ty = threadIdx.y;

#pragma unroll
    for (int k = 0; k < 64; k += 8)
        tile[tx][ty + k] = X[(size_t)(b0 + ty + k) * PIX + (p0 + tx)];
    __syncthreads();

    const int w = ty;
#pragma unroll
    for (int i = 0; i < 4; i++) {
        const int pl = w * 4 + i;
        const int p  = p0 + pl;
        const int y  = p >> 6, x = p & 63;
        const __half2 v = __floats2half2_rn(tile[pl][2 * tx],
                                            tile[pl][2 * tx + 1]);
        *(__half2*)(g_xh + (size_t)((y + PAD) * PW + (x + PAD)) * BATCH
                         + b0 + 2 * tx) = v;
    }
}

// ---------------------------------------------------------------------------
// Packed f32x2 helpers (Blackwell packed-FP32 pipe: 2x FFMA throughput)
// ---------------------------------------------------------------------------
__device__ __forceinline__ unsigned long long ffma2(unsigned long long a,
                                                    unsigned long long b,
                                                    unsigned long long c) {
    unsigned long long d;
    asm("fma.rn.f32x2 %0, %1, %2, %3;" : "=l"(d) : "l"(a), "l"(b), "l"(c));
    return d;
}
__device__ __forceinline__ unsigned long long fmul2(unsigned long long a,
                                                    unsigned long long b) {
    unsigned long long d;
    asm("mul.rn.f32x2 %0, %1, %2;" : "=l"(d) : "l"(a), "l"(b));
    return d;
}
__device__ __forceinline__ unsigned long long pack2(float x, float y) {
    unsigned long long r;
    asm("mov.b64 %0, {%1, %2};" : "=l"(r) : "f"(x), "f"(y));
    return r;
}
__device__ __forceinline__ float2 unpack2(unsigned long long v) {
    float2 r;
    asm("mov.b64 {%0, %1}, %2;" : "=f"(r.x), "=f"(r.y) : "l"(v));
    return r;
}
__device__ __forceinline__ uint32_t smem_u32(const void* p) {
    uint32_t a;
    asm("{ .reg .u64 t; cvta.to.shared.u64 t, %1; cvt.u32.u64 %0, t; }"
        : "=r"(a) : "l"(p));
    return a;
}
__device__ __forceinline__ void cp16(uint32_t dst, const void* src) {
    asm volatile("cp.async.cg.shared.global [%0], [%1], 16;"
                 :: "r"(dst), "l"(src));
}
__device__ __forceinline__ void cp_commit() {
    asm volatile("cp.async.commit_group;" ::: "memory");
}

// ---------------------------------------------------------------------------
// Kernel 2: per (filter, batch-chunk) fused 5x5 conv (6x6 of the 7x7 outputs
// the pool reads) + bias + 3x3/3 maxpool.  Window rows are staged into a
// 4-stage SMEM ring with cp.async (prefetch distance 3 rows ~= 900+ cyc,
// fully hiding L2 latency with zero register cost); compute is conflict-free
// LDS.32 + packed f32x2 FMAs.  One __syncthreads per row.
// ---------------------------------------------------------------------------
__global__ void __launch_bounds__(128, 4) filters_conv_kernel(
    const float* __restrict__ W,      // [NF, 25]
    const float* __restrict__ bias,   // [NF]
    const int*   __restrict__ pos,    // [NF, 2]
    float*       __restrict__ out)    // [B, NF*4]
{
    __shared__ __align__(16) unsigned char rbuf[NSTG][ROWB];  // 20 KB ring
    __shared__ unsigned long long wsh[25];

    const int tid = threadIdx.x;
    const int f   = blockIdx.x;
    const int b   = blockIdx.y * 256 + tid * 2;       // this thread's batches

    const int pi = __ldg(&pos[2 * f]);
    const int pj = __ldg(&pos[2 * f + 1]);

    if (tid < 25) {
        const float w = W[f * 25 + tid];
        wsh[tid] = pack2(w, w);
    }

    // Global base of this block's window slice (batch-chunk offset included).
    const char* gbase = (const char*)g_xh +
        ((size_t)(pi * PW + pj) * BATCH + blockIdx.y * 256) * sizeof(__half);
    const uint32_t rbase = smem_u32(rbuf);

    // Prefetch one row (10 px * 512 B = 320 x 16B chunks, 2.5 per thread).
    // dst is linear in chunk id q; src: pixel stride 2048 B, inner 16 B.
    auto prefetch = [&](int rr, int stage) {
        const char* rsrc = gbase + (size_t)rr * (PW * BATCH * 2);
        const uint32_t rdst = rbase + stage * ROWB;
#pragma unroll
        for (int k = 0; k < 2; k++) {
            const int q = tid + k * 128;
            cp16(rdst + q * 16, rsrc + (q >> 5) * 2048 + (q & 31) * 16);
        }
        if (tid < 64) {
            const int q = tid + 256;
            cp16(rdst + q * 16, rsrc + (q >> 5) * 2048 + (q & 31) * 16);
        }
        cp_commit();
    };

    prefetch(0, 0);
    prefetch(1, 1);
    prefetch(2, 2);

    unsigned long long acc[36];              // <=30 live at any point
    float pm0[4], pm1[4];                    // running 2x2 max per batch
#pragma unroll
    for (int q = 0; q < 4; q++) { pm0[q] = -FLT_MAX; pm1[q] = -FLT_MAX; }

#pragma unroll
    for (int r = 0; r < 10; r++) {
        // Row r's group is complete when pending groups <= outstanding rows.
        if (r <= 7)      asm volatile("cp.async.wait_group 2;" ::: "memory");
        else if (r == 8) asm volatile("cp.async.wait_group 1;" ::: "memory");
        else             asm volatile("cp.async.wait_group 0;" ::: "memory");
        __syncthreads();   // row r visible to all; prior buffer reads done

        // Prefetch row r+3 into stage (r+3)&3 (last read finished at r-1).
        if (r + 3 < 10) prefetch(r + 3, (r + 3) & (NSTG - 1));

        // Load this thread's 10 half2 pixels of row r (conflict-free LDS.32).
        const __half2* rp = (const __half2*)rbuf[r & (NSTG - 1)];
        unsigned long long row[10];
#pragma unroll
        for (int c = 0; c < 10; c++) {
            const float2 fv = __half22float2(rp[c * 128 + tid]);
            row[c] = pack2(fv.x, fv.y);
        }

        // Row r feeds conv rows oy with ky = r - oy in [0,4].
#pragma unroll
        for (int oy = 0; oy < 6; oy++) {
            const int ky = r - oy;
            if (ky < 0 || ky > 4) continue;       // compile-time pruned
#pragma unroll
            for (int kx = 0; kx < 5; kx++) {
                const unsigned long long w = wsh[ky * 5 + kx];
#pragma unroll
                for (int ox = 0; ox < 6; ox++) {
                    if (ky == 0 && kx == 0)
                        acc[oy * 6 + ox] = fmul2(row[ox], w);
                    else
                        acc[oy * 6 + ox] = ffma2(row[ox + kx], w,
                                                 acc[oy * 6 + ox]);
                }
            }
        }

        // Conv row oy = r-4 complete: fold into pooled max, free its accs.
        if (r >= 4) {
            const int oy = r - 4;
            const int py = oy / 3;               // compile-time
#pragma unroll
            for (int px = 0; px < 2; px++) {
#pragma unroll
                for (int dx = 0; dx < 3; dx++) {
                    const float2 v = unpack2(acc[oy * 6 + 3 * px + dx]);
                    pm0[py * 2 + px] = fmaxf(pm0[py * 2 + px], v.x);
                    pm1[py * 2 + px] = fmaxf(pm1[py * 2 + px], v.y);
                }
            }
        }
    }

    // bias (uniform -> add after max) and one float4 store per batch.
    const float bv = __ldg(&bias[f]);
    float4* o0 = (float4*)(out + (size_t)b * (NF * 4) + f * 4);
    float4* o1 = (float4*)(out + (size_t)(b + 1) * (NF * 4) + f * 4);
    *o0 = make_float4(pm0[0] + bv, pm0[1] + bv, pm0[2] + bv, pm0[3] + bv);
    *o1 = make_float4(pm1[0] + bv, pm1[1] + bv, pm1[2] + bv, pm1[3] + bv);
}

// ---------------------------------------------------------------------------
// kernel_launch: transpose/convert + conv. Graph-capturable, allocation-free
// (scratch is a zero-initialized __device__ global; border never written).
// ---------------------------------------------------------------------------
extern "C" void kernel_launch(void* const* d_in, const int* in_sizes, int n_in,
                              void* d_out, int out_size) {
    (void)in_sizes; (void)n_in; (void)out_size;
    const float* X    = (const float*)d_in[0];
    const float* W    = (const float*)d_in[1];
    const float* bias = (const float*)d_in[2];
    const int*   pos  = (const int*)d_in[3];
    float*       out  = (float*)d_out;

    dim3 tb(32, 8);
    dim3 tg(PIX / 32, BATCH / 64);         // (128, 16)
    xt_transpose_kernel<<<tg, tb>>>(X);

    dim3 cg(NF, BATCH / 256);              // (1024, 4)
    filters_conv_kernel<<<cg, 128>>>(W, bias, pos, out);
}

// round 13
// speedup vs baseline: 1.2230x; 1.2230x over previous
#include <cuda_runtime.h>
#include <cuda_fp16.h>
#include <cstdint>
#include <cfloat>

// Problem constants
#define NF    1024
#define BATCH 1024
#define HW    64
#define PIX   (HW * HW)     // 4096
#define PAD   3
#define PW    70            // padded side
#define PPIX  (PW * PW)     // 4900

// 10 MB scratch: zero-PADDED image, fp16, transposed to [padded_pixel][batch].
// __device__ globals are zero-initialized at module load (fp16 zero == 0x0000)
// and the transpose never writes the 3-wide border, so the conv loop needs no
// bounds checks, no border kernel, and no per-load address math.
__device__ __half g_xh[(size_t)PPIX * BATCH];

// ---------------------------------------------------------------------------
// Kernel 1: transpose + fp32->fp16 convert.  X [B, 4096] -> g_xh interior.
// ---------------------------------------------------------------------------
__global__ void xt_transpose_kernel(const float* __restrict__ X) {
    __shared__ float tile[32][65];          // [pixel_local][batch_local]
    const int p0 = blockIdx.x * 32;
    const int b0 = blockIdx.y * 64;
    const int tx = threadIdx.x;             // block (32, 8)
    const int ty = threadIdx.y;

#pragma unroll
    for (int k = 0; k < 64; k += 8)         // coalesced 128B loads
        tile[tx][ty + k] = X[(size_t)(b0 + ty + k) * PIX + (p0 + tx)];
    __syncthreads();

    const int w = ty;
#pragma unroll
    for (int i = 0; i < 4; i++) {
        const int pl = w * 4 + i;
        const int p  = p0 + pl;
        const int y  = p >> 6, x = p & 63;
        const __half2 v = __floats2half2_rn(tile[pl][2 * tx],
                                            tile[pl][2 * tx + 1]);
        *(__half2*)(g_xh + (size_t)((y + PAD) * PW + (x + PAD)) * BATCH
                         + b0 + 2 * tx) = v;
    }
}

// ---------------------------------------------------------------------------
// Packed f32x2 helpers (Blackwell packed-FP32 pipe: 2x FFMA throughput)
// ---------------------------------------------------------------------------
__device__ __forceinline__ unsigned long long ffma2(unsigned long long a,
                                                    unsigned long long b,
                                                    unsigned long long c) {
    unsigned long long d;
    asm("fma.rn.f32x2 %0, %1, %2, %3;" : "=l"(d) : "l"(a), "l"(b), "l"(c));
    return d;
}
__device__ __forceinline__ unsigned long long fmul2(unsigned long long a,
                                                    unsigned long long b) {
    unsigned long long d;
    asm("mul.rn.f32x2 %0, %1, %2;" : "=l"(d) : "l"(a), "l"(b));
    return d;
}
__device__ __forceinline__ unsigned long long pack2(float x, float y) {
    unsigned long long r;
    asm("mov.b64 %0, {%1, %2};" : "=l"(r) : "f"(x), "f"(y));
    return r;
}
__device__ __forceinline__ float2 unpack2(unsigned long long v) {
    float2 r;
    asm("mov.b64 {%0, %1}, %2;" : "=f"(r.x), "=f"(r.y) : "l"(v));
    return r;
}

// ---------------------------------------------------------------------------
// Kernel 2: per (filter, batch-pair) fused 5x5 conv + bias + 3x3/3 maxpool,
// computed in TWO column passes (output cols 0-2, then 3-5) so that at most
// 15 packed accumulators are live -> ~75 regs -> 6 resident blocks/SM
// (37.5% occupancy, enough warps to hide L2 latency of the row loads).
// Each thread owns TWO adjacent batches (packed f32x2 math); weights live in
// SMEM (broadcast, conflict-free); conv rows fold into the running 2x2 max
// as soon as they complete.
// ---------------------------------------------------------------------------
__global__ void __launch_bounds__(128, 6) filters_conv_kernel(
    const float* __restrict__ W,      // [NF, 25]
    const float* __restrict__ bias,   // [NF]
    const int*   __restrict__ pos,    // [NF, 2]
    float*       __restrict__ out)    // [B, NF*4]
{
    __shared__ unsigned long long wsh[25];   // broadcast-packed (w, w)

    const int tid = threadIdx.x;
    const int f = blockIdx.x;
    const int b = blockIdx.y * 256 + tid * 2;   // even -> 4B aligned
    const int pi = __ldg(&pos[2 * f]);
    const int pj = __ldg(&pos[2 * f + 1]);

    if (tid < 25) {
        const float w = W[f * 25 + tid];
        wsh[tid] = pack2(w, w);
    }
    __syncthreads();

    // Window base pointer; all loads below use compile-time byte offsets.
    const char* p0 = (const char*)g_xh +
                     ((size_t)(pi * PW + pj) * BATCH + b) * sizeof(__half);

    float pm0[4], pm1[4];                    // final 2x2 max per batch
#pragma unroll
    for (int q = 0; q < 4; q++) { pm0[q] = -FLT_MAX; pm1[q] = -FLT_MAX; }

    // ---- Two column passes: pass px covers output cols 3px..3px+2, which
    // read window cols 3px..3px+6 of all 10 rows. ----
#pragma unroll
    for (int px = 0; px < 2; px++) {
        unsigned long long acc[18];          // <=15 live at any point

#pragma unroll
        for (int r = 0; r < 10; r++) {
            // 7 window pixels of row r for this column pass.
            unsigned long long row[7];
#pragma unroll
            for (int c = 0; c < 7; c++) {
                const __half2 h = *(const __half2*)(
                    p0 + (size_t)((r * PW + 3 * px + c) * BATCH)
                             * sizeof(__half));
                const float2 fv = __half22float2(h);
                row[c] = pack2(fv.x, fv.y);
            }

            // Row r feeds conv rows oy with ky = r - oy in [0,4].
#pragma unroll
            for (int oy = 0; oy < 6; oy++) {
                const int ky = r - oy;
                if (ky < 0 || ky > 4) continue;   // compile-time pruned
#pragma unroll
                for (int kx = 0; kx < 5; kx++) {
                    const unsigned long long w = wsh[ky * 5 + kx];
#pragma unroll
                    for (int ox = 0; ox < 3; ox++) {
                        if (ky == 0 && kx == 0)
                            acc[oy * 3 + ox] = fmul2(row[ox], w);
                        else
                            acc[oy * 3 + ox] = ffma2(row[ox + kx], w,
                                                     acc[oy * 3 + ox]);
                    }
                }
            }

            // Conv row oy = r-4 complete: fold into pooled max, free accs.
            if (r >= 4) {
                const int oy = r - 4;
                const int py = oy / 3;           // compile-time
#pragma unroll
                for (int dx = 0; dx < 3; dx++) {
                    const float2 v = unpack2(acc[oy * 3 + dx]);
                    pm0[py * 2 + px] = fmaxf(pm0[py * 2 + px], v.x);
                    pm1[py * 2 + px] = fmaxf(pm1[py * 2 + px], v.y);
                }
            }
        }
    }

    // bias (uniform -> add after max) and one float4 store per batch.
    const float bv = __ldg(&bias[f]);
    float4* o0 = (float4*)(out + (size_t)b * (NF * 4) + f * 4);
    float4* o1 = (float4*)(out + (size_t)(b + 1) * (NF * 4) + f * 4);
    *o0 = make_float4(pm0[0] + bv, pm0[1] + bv, pm0[2] + bv, pm0[3] + bv);
    *o1 = make_float4(pm1[0] + bv, pm1[1] + bv, pm1[2] + bv, pm1[3] + bv);
}

// ---------------------------------------------------------------------------
// kernel_launch: transpose/convert + conv. Graph-capturable, allocation-free
// (scratch is a zero-initialized __device__ global; border never written).
// ---------------------------------------------------------------------------
extern "C" void kernel_launch(void* const* d_in, const int* in_sizes, int n_in,
                              void* d_out, int out_size) {
    (void)in_sizes; (void)n_in; (void)out_size;
    const float* X    = (const float*)d_in[0];
    const float* W    = (const float*)d_in[1];
    const float* bias = (const float*)d_in[2];
    const int*   pos  = (const int*)d_in[3];
    float*       out  = (float*)d_out;

    dim3 tb(32, 8);
    dim3 tg(PIX / 32, BATCH / 64);         // (128, 16)
    xt_transpose_kernel<<<tg, tb>>>(X);

    dim3 cg(NF, BATCH / 256);              // (1024, 4)
    filters_conv_kernel<<<cg, 128>>>(W, bias, pos, out);
}

// round 14
// speedup vs baseline: 1.2301x; 1.0059x over previous
#include <cuda_runtime.h>
#include <cuda_fp16.h>
#include <cstdint>
#include <cfloat>

// Problem constants
#define NF    1024
#define BATCH 1024
#define HW    64
#define PIX   (HW * HW)     // 4096
#define PAD   3
#define PW    70            // padded side
#define PPIX  (PW * PW)     // 4900

// 10 MB scratch: zero-PADDED image, fp16, transposed to [padded_pixel][batch].
// __device__ globals are zero-initialized at module load (fp16 zero == 0x0000)
// and the transpose never writes the 3-wide border, so the conv loop needs no
// bounds checks, no border kernel, and no per-load address math.
__device__ __half g_xh[(size_t)PPIX * BATCH];

// ---------------------------------------------------------------------------
// Kernel 1: transpose + fp32->fp16 convert.  X [B, 4096] -> g_xh interior.
// ---------------------------------------------------------------------------
__global__ void xt_transpose_kernel(const float* __restrict__ X) {
    __shared__ float tile[32][65];          // [pixel_local][batch_local]
    const int p0 = blockIdx.x * 32;
    const int b0 = blockIdx.y * 64;
    const int tx = threadIdx.x;             // block (32, 8)
    const int ty = threadIdx.y;

#pragma unroll
    for (int k = 0; k < 64; k += 8)         // coalesced 128B loads
        tile[tx][ty + k] = X[(size_t)(b0 + ty + k) * PIX + (p0 + tx)];
    __syncthreads();

    const int w = ty;
#pragma unroll
    for (int i = 0; i < 4; i++) {
        const int pl = w * 4 + i;
        const int p  = p0 + pl;
        const int y  = p >> 6, x = p & 63;
        const __half2 v = __floats2half2_rn(tile[pl][2 * tx],
                                            tile[pl][2 * tx + 1]);
        *(__half2*)(g_xh + (size_t)((y + PAD) * PW + (x + PAD)) * BATCH
                         + b0 + 2 * tx) = v;
    }
}

// ---------------------------------------------------------------------------
// Packed f32x2 helpers (Blackwell packed-FP32 pipe: 2x FFMA throughput)
// ---------------------------------------------------------------------------
__device__ __forceinline__ unsigned long long ffma2(unsigned long long a,
                                                    unsigned long long b,
                                                    unsigned long long c) {
    unsigned long long d;
    asm("fma.rn.f32x2 %0, %1, %2, %3;" : "=l"(d) : "l"(a), "l"(b), "l"(c));
    return d;
}
__device__ __forceinline__ unsigned long long fmul2(unsigned long long a,
                                                    unsigned long long b) {
    unsigned long long d;
    asm("mul.rn.f32x2 %0, %1, %2;" : "=l"(d) : "l"(a), "l"(b));
    return d;
}
__device__ __forceinline__ unsigned long long pack2(float x, float y) {
    unsigned long long r;
    asm("mov.b64 %0, {%1, %2};" : "=l"(r) : "f"(x), "f"(y));
    return r;
}
__device__ __forceinline__ float2 unpack2(unsigned long long v) {
    float2 r;
    asm("mov.b64 {%0, %1}, %2;" : "=f"(r.x), "=f"(r.y) : "l"(v));
    return r;
}

// ---------------------------------------------------------------------------
// Kernel 2: per (filter, batch-pair) fused 5x5 conv + bias + 3x3/3 maxpool,
// computed in TWO column passes (output cols 0-2, then 3-5) so that at most
// 15 packed accumulators are live -> ~75 regs -> 6 resident blocks/SM
// (37.5% occupancy, enough warps to hide L2 latency of the row loads).
// Each thread owns TWO adjacent batches (packed f32x2 math); weights live in
// SMEM (broadcast, conflict-free); conv rows fold into the running 2x2 max
// as soon as they complete.
// ---------------------------------------------------------------------------
__global__ void __launch_bounds__(128, 6) filters_conv_kernel(
    const float* __restrict__ W,      // [NF, 25]
    const float* __restrict__ bias,   // [NF]
    const int*   __restrict__ pos,    // [NF, 2]
    float*       __restrict__ out)    // [B, NF*4]
{
    __shared__ unsigned long long wsh[25];   // broadcast-packed (w, w)

    const int tid = threadIdx.x;
    const int f = blockIdx.x;
    const int b = blockIdx.y * 256 + tid * 2;   // even -> 4B aligned
    const int pi = __ldg(&pos[2 * f]);
    const int pj = __ldg(&pos[2 * f + 1]);

    if (tid < 25) {
        const float w = W[f * 25 + tid];
        wsh[tid] = pack2(w, w);
    }
    __syncthreads();

    // Window base pointer; all loads below use compile-time byte offsets.
    const char* p0 = (const char*)g_xh +
                     ((size_t)(pi * PW + pj) * BATCH + b) * sizeof(__half);

    float pm0[4], pm1[4];                    // final 2x2 max per batch
#pragma unroll
    for (int q = 0; q < 4; q++) { pm0[q] = -FLT_MAX; pm1[q] = -FLT_MAX; }

    // ---- Two column passes: pass px covers output cols 3px..3px+2, which
    // read window cols 3px..3px+6 of all 10 rows. ----
#pragma unroll
    for (int px = 0; px < 2; px++) {
        unsigned long long acc[18];          // <=15 live at any point

#pragma unroll
        for (int r = 0; r < 10; r++) {
            // 7 window pixels of row r for this column pass.
            unsigned long long row[7];
#pragma unroll
            for (int c = 0; c < 7; c++) {
                const __half2 h = *(const __half2*)(
                    p0 + (size_t)((r * PW + 3 * px + c) * BATCH)
                             * sizeof(__half));
                const float2 fv = __half22float2(h);
                row[c] = pack2(fv.x, fv.y);
            }

            // Row r feeds conv rows oy with ky = r - oy in [0,4].
#pragma unroll
            for (int oy = 0; oy < 6; oy++) {
                const int ky = r - oy;
                if (ky < 0 || ky > 4) continue;   // compile-time pruned
#pragma unroll
                for (int kx = 0; kx < 5; kx++) {
                    const unsigned long long w = wsh[ky * 5 + kx];
#pragma unroll
                    for (int ox = 0; ox < 3; ox++) {
                        if (ky == 0 && kx == 0)
                            acc[oy * 3 + ox] = fmul2(row[ox], w);
                        else
                            acc[oy * 3 + ox] = ffma2(row[ox + kx], w,
                                                     acc[oy * 3 + ox]);
                    }
                }
            }

            // Conv row oy = r-4 complete: fold into pooled max, free accs.
            if (r >= 4) {
                const int oy = r - 4;
                const int py = oy / 3;           // compile-time
#pragma unroll
                for (int dx = 0; dx < 3; dx++) {
                    const float2 v = unpack2(acc[oy * 3 + dx]);
                    pm0[py * 2 + px] = fmaxf(pm0[py * 2 + px], v.x);
                    pm1[py * 2 + px] = fmaxf(pm1[py * 2 + px], v.y);
                }
            }
        }
    }

    // bias (uniform -> add after max) and one float4 store per batch.
    const float bv = __ldg(&bias[f]);
    float4* o0 = (float4*)(out + (size_t)b * (NF * 4) + f * 4);
    float4* o1 = (float4*)(out + (size_t)(b + 1) * (NF * 4) + f * 4);
    *o0 = make_float4(pm0[0] + bv, pm0[1] + bv, pm0[2] + bv, pm0[3] + bv);
    *o1 = make_float4(pm1[0] + bv, pm1[1] + bv, pm1[2] + bv, pm1[3] + bv);
}

// ---------------------------------------------------------------------------
// kernel_launch: transpose/convert + conv. Graph-capturable, allocation-free
// (scratch is a zero-initialized __device__ global; border never written).
// ---------------------------------------------------------------------------
extern "C" void kernel_launch(void* const* d_in, const int* in_sizes, int n_in,
                              void* d_out, int out_size) {
    (void)in_sizes; (void)n_in; (void)out_size;
    const float* X    = (const float*)d_in[0];
    const float* W    = (const float*)d_in[1];
    const float* bias = (const float*)d_in[2];
    const int*   pos  = (const int*)d_in[3];
    float*       out  = (float*)d_out;

    dim3 tb(32, 8);
    dim3 tg(PIX / 32, BATCH / 64);         // (128, 16)
    xt_transpose_kernel<<<tg, tb>>>(X);

    dim3 cg(NF, BATCH / 256);              // (1024, 4)
    filters_conv_kernel<<<cg, 128>>>(W, bias, pos, out);
}